// round 16
// baseline (speedup 1.0000x reference)
#include <cuda_runtime.h>

// Soft-DTW (gamma=1), 64 batches of 1024x1024.
// FORWARD/BACKWARD SPLIT (proven R15): 128 CTAs (64 fwd + 64 rev), each runs
// the warp-skewed block pipeline over diags 0..1023 only, dumps diag-1022/1023
// values; combine_kernel does the exact cut softmin; reduce averages.
// R16: BALANCED BAND PAIRING. 8 warps/CTA; warp w owns band w AND band 15-w
// (64 rows each, 2 rows/thread). Band b runs block t at superstep t+b, so the
// strip protocol (double-buffered bufk indexed by band, one __syncthreads per
// superstep) is unchanged. Per-warp load = (64-4w)+(4w+4) = 68 blocks constant
// -> all 4 SMSPs carry 136 blocks (was 112..160): removes skew imbalance.

#define NBATCH 64
#define NPTS   1024
#define TPB    256            // dtw + combine blocks
#define NW     8
#define NBANDS 16
#define KB     16
#define NBLK   64             // diagonals 0..1023 only
#define NSUP   (NBLK + NBANDS - 1)
#define BIGV   1.0e30f
#define SENT   1.0e17f
#define LN2F   0.69314718055994531f
#define PAD    64
#define SCPN   1100           // scp indices used: [1, 1088]

__device__ float g_partial[NBATCH];
__device__ float g_cut[NBATCH][4][NPTS];   // 0=f1022, 1=f1023, 2=r1022, 3=r1023

__device__ __forceinline__ float ex2f(float x) {
    float r; asm("ex2.approx.ftz.f32 %0, %1;" : "=f"(r) : "f"(x)); return r;
}
__device__ __forceinline__ float lg2f(float x) {
    float r; asm("lg2.approx.ftz.f32 %0, %1;" : "=f"(r) : "f"(x)); return r;
}

// softmin in log2 domain: one exp arg is always 0 -> 2 ex2 + 1 lg2.
__device__ __forceinline__ float cellv(float a, float bq, float c, float Dl) {
    float t1  = fminf(a, bq);
    float t2  = fmaxf(a, bq);
    float mn  = fminf(t1, c);
    float mx  = fmaxf(t2, c);
    float mid = fminf(t2, fmaxf(t1, c));
    float s   = 1.0f + (ex2f(mn - mid) + ex2f(mn - mx));
    return Dl + (mn - lg2f(s));
}

typedef float BufT[2][NBANDS][KB + 1];

// One 16-diag block for one band. Strip rows indexed by band.
template<bool LAST>
__device__ __forceinline__ void run_block16(
    BufT& bufk, int slot, int band, int lane,
    const float4* pc, float4& cb,
    float& cur_a, float& cur_b, float& cur_a_old, float& nb2,
    float m2ax, float m2ay, float s2a,
    float m2bx, float m2by, float s2b,
    float& o22a, float& o22b)
{
    #pragma unroll
    for (int k = 0; k < KB; ++k) {
        float nb1 = __shfl_up_sync(0xFFFFFFFFu, cur_b, 1);
        if (lane == 0) nb1 = (band == 0) ? BIGV : bufk[slot][band - 1][k];

        float4 ca = pc[k];
        float Dla = fmaf(m2ay, ca.y, fmaf(m2ax, ca.x, s2a + ca.z));
        float Dlb = fmaf(m2by, cb.y, fmaf(m2bx, cb.x, s2b + cb.z));

        float new_a = cellv(nb2,       nb1,   cur_a, Dla);
        float new_b = cellv(cur_a_old, cur_a, cur_b, Dlb);

        if (lane == 31) bufk[slot][band][k + 1] = new_b;

        nb2 = nb1; cur_a_old = cur_a; cur_a = new_a; cur_b = new_b;
        cb = ca;
        if (LAST && k == KB - 2) { o22a = cur_a; o22b = cur_b; }  // diag 1022
    }
}

__global__ __launch_bounds__(TPB, 1)
void dtw_kernel(const float* __restrict__ snake, const float* __restrict__ contour)
{
    __shared__ float4 scp[SCPN];      // (cx, cy, cx^2+cy^2, 0), sentinel outside
    __shared__ BufT   bufk;

    const int tid  = threadIdx.x;
    const int lane = tid & 31;
    const int wid  = tid >> 5;        // 0..7
    const int rev  = blockIdx.x & 1;  // 0 = forward, 1 = reversed sequences
    const int b    = blockIdx.x >> 1;
    const float SCALE = 1.2011224087864498f;   // sqrt(log2 e)

    // scp[idx] <-> jp = idx - PAD; valid contour at jp in [1,1024].
    for (int k = tid; k < SCPN; k += TPB) {
        int j = k - PAD;
        float cx = SENT, cy = SENT;
        if (j >= 1 && j <= NPTS) {
            int src = rev ? (NPTS - j) : (j - 1);
            float2 c = ((const float2*)contour)[b * NPTS + src];
            cx = c.x * SCALE; cy = c.y * SCALE;
        }
        scp[k] = make_float4(cx, cy, fmaf(cx, cx, cy * cy), 0.f);
    }
    for (int k = tid; k < 2 * NBANDS * (KB + 1); k += TPB)
        ((float*)bufk)[k] = BIGV;

    // Per-band snake rows (2 rows/thread). Band b: rows 64b+2l, 64b+2l+1
    // (in this CTA's orientation; rev flips the sequence).
    const int bandA = wid;
    const int bandB = 15 - wid;
    const int rowA  = 64 * bandA + 2 * lane;
    const int rowB  = 64 * bandB + 2 * lane;

    float sAax, sAay, sAbx, sAby, sBax, sBay, sBbx, sBby;
    if (!rev) {
        float4 s4 = ((const float4*)snake)[(b * NPTS + rowA) >> 1];
        sAax = s4.x * SCALE; sAay = s4.y * SCALE;
        sAbx = s4.z * SCALE; sAby = s4.w * SCALE;
        float4 t4 = ((const float4*)snake)[(b * NPTS + rowB) >> 1];
        sBax = t4.x * SCALE; sBay = t4.y * SCALE;
        sBbx = t4.z * SCALE; sBby = t4.w * SCALE;
    } else {
        // rev row r = orig row 1023-r; rows (rowA, rowA+1) -> orig (1023-rowA, 1022-rowA)
        float4 s4 = ((const float4*)snake)[(b * NPTS + (1022 - rowA)) >> 1];
        sAax = s4.z * SCALE; sAay = s4.w * SCALE;   // orig 1023-rowA
        sAbx = s4.x * SCALE; sAby = s4.y * SCALE;   // orig 1022-rowA
        float4 t4 = ((const float4*)snake)[(b * NPTS + (1022 - rowB)) >> 1];
        sBax = t4.z * SCALE; sBay = t4.w * SCALE;
        sBbx = t4.x * SCALE; sBby = t4.y * SCALE;
    }
    const float mAax = -2.f * sAax, mAay = -2.f * sAay, sA2a = fmaf(sAax, sAax, sAay * sAay);
    const float mAbx = -2.f * sAbx, mAby = -2.f * sAby, sA2b = fmaf(sAbx, sAbx, sAby * sAby);
    const float mBax = -2.f * sBax, mBay = -2.f * sBay, sB2a = fmaf(sBax, sBax, sBay * sBay);
    const float mBbx = -2.f * sBbx, mBby = -2.f * sBby, sB2b = fmaf(sBbx, sBbx, sBby * sBby);

    __syncthreads();

    float curAa = BIGV, curAb = BIGV, oldAa = BIGV, nb2A = BIGV;
    float curBa = BIGV, curBb = BIGV, oldBa = BIGV, nb2B = BIGV;
    if (tid == 0) nb2A = 0.0f;        // band 0, row 0: R(-1,-1)=0 seed

    const int tLoA = 4 * bandA;
    const int tLoB = 4 * bandB;

    const float4* pcA = &scp[tLoA * KB - rowA + 1 + PAD];
    const float4* pcB = &scp[tLoB * KB - rowB + 1 + PAD];
    float4 cbA = pcA[-1];
    float4 cbB = pcB[-1];
    float o22a = BIGV, o22b = BIGV;

    for (int s = 0; s < NSUP; ++s) {
        // Band A (= band wid), block tA = s - bandA.
        const int tA = s - bandA;
        if (tA >= tLoA && tA < NBLK) {
            const int slot = tA & 1;
            if (lane == 31) bufk[slot][bandA][0] = curAb;   // carry: diag t*KB-1
            if (tA < NBLK - 1) {
                run_block16<false>(bufk, slot, bandA, lane, pcA, cbA,
                                   curAa, curAb, oldAa, nb2A,
                                   mAax, mAay, sA2a, mAbx, mAby, sA2b, o22a, o22b);
            } else {
                run_block16<true>(bufk, slot, bandA, lane, pcA, cbA,
                                  curAa, curAb, oldAa, nb2A,
                                  mAax, mAay, sA2a, mAbx, mAby, sA2b, o22a, o22b);
                g_cut[b][2 * rev + 0][rowA]     = o22a;
                g_cut[b][2 * rev + 0][rowA + 1] = o22b;
                g_cut[b][2 * rev + 1][rowA]     = curAa;
                g_cut[b][2 * rev + 1][rowA + 1] = curAb;
            }
            pcA += KB;
        }
        // Band B (= band 15-wid), block tB = s - bandB.
        const int tB = s - bandB;
        if (tB >= tLoB && tB < NBLK) {
            const int slot = tB & 1;
            if (lane == 31) bufk[slot][bandB][0] = curBb;
            if (tB < NBLK - 1) {
                run_block16<false>(bufk, slot, bandB, lane, pcB, cbB,
                                   curBa, curBb, oldBa, nb2B,
                                   mBax, mBay, sB2a, mBbx, mBby, sB2b, o22a, o22b);
            } else {
                run_block16<true>(bufk, slot, bandB, lane, pcB, cbB,
                                  curBa, curBb, oldBa, nb2B,
                                  mBax, mBay, sB2a, mBbx, mBby, sB2b, o22a, o22b);
                g_cut[b][2 * rev + 0][rowB]     = o22a;
                g_cut[b][2 * rev + 0][rowB + 1] = o22b;
                g_cut[b][2 * rev + 1][rowB]     = curBa;
                g_cut[b][2 * rev + 1][rowB + 1] = curBb;
            }
            pcB += KB;
        }
        __syncthreads();
    }
}

__global__ __launch_bounds__(TPB)
void combine_kernel(const float* __restrict__ snake, const float* __restrict__ contour)
{
    __shared__ float red[64];
    const int b   = blockIdx.x;
    const int tid = threadIdx.x;
    const int lane = tid & 31, wid = tid >> 5;
    const float LOG2E = 1.4426950408889634f;

    float t[8];
    #pragma unroll
    for (int q = 0; q < 8; ++q) t[q] = BIGV;

    #pragma unroll
    for (int q = 0; q < 4; ++q) {
        int i = tid + q * TPB;                       // 0..1023
        float2 s = ((const float2*)snake)[b * NPTS + i];
        float2 c = ((const float2*)contour)[b * NPTS + (NPTS - 1 - i)];
        float dx = s.x - c.x, dy = s.y - c.y;
        float Dl = LOG2E * fmaf(dy, dy, dx * dx);
        t[q] = g_cut[b][1][i] + g_cut[b][3][NPTS - 1 - i] - Dl;
    }
    #pragma unroll
    for (int q = 0; q < 4; ++q) {
        int i = tid + q * TPB;
        if (i < NPTS - 1)                            // 0..1022
            t[4 + q] = g_cut[b][0][i] + g_cut[b][2][NPTS - 2 - i];
    }

    float m = t[0];
    #pragma unroll
    for (int q = 1; q < 8; ++q) m = fminf(m, t[q]);
    #pragma unroll
    for (int off = 16; off > 0; off >>= 1)
        m = fminf(m, __shfl_xor_sync(0xFFFFFFFFu, m, off));
    if (lane == 0) red[wid] = m;
    __syncthreads();
    if (tid == 0) {
        float mm = red[0];
        for (int w = 1; w < TPB / 32; ++w) mm = fminf(mm, red[w]);
        red[0] = mm;
    }
    __syncthreads();
    m = red[0];

    float S = 0.f;
    #pragma unroll
    for (int q = 0; q < 8; ++q) S += ex2f(m - t[q]);
    #pragma unroll
    for (int off = 16; off > 0; off >>= 1)
        S += __shfl_xor_sync(0xFFFFFFFFu, S, off);
    if (lane == 0) red[32 + wid] = S;
    __syncthreads();
    if (tid == 0) {
        float ss = 0.f;
        for (int w = 0; w < TPB / 32; ++w) ss += red[32 + w];
        g_partial[b] = (m - lg2f(ss)) * LN2F;        // softmin -> ln units
    }
}

__global__ void reduce_kernel(float* __restrict__ out)
{
    float v = g_partial[threadIdx.x] + g_partial[threadIdx.x + 32];
    #pragma unroll
    for (int off = 16; off > 0; off >>= 1)
        v += __shfl_down_sync(0xFFFFFFFFu, v, off);
    if (threadIdx.x == 0)
        out[0] = v * (1.0f / NBATCH);
}

extern "C" void kernel_launch(void* const* d_in, const int* in_sizes, int n_in,
                              void* d_out, int out_size)
{
    const float* snake   = (const float*)d_in[0];
    const float* contour = (const float*)d_in[1];
    float* out = (float*)d_out;

    dtw_kernel<<<NBATCH * 2, TPB>>>(snake, contour);
    combine_kernel<<<NBATCH, TPB>>>(snake, contour);
    reduce_kernel<<<1, 32>>>(out);
}

// round 17
// speedup vs baseline: 1.0314x; 1.0314x over previous
#include <cuda_runtime.h>

// Soft-DTW (gamma=1), 64 batches of 1024x1024.
// FORWARD/BACKWARD SPLIT (proven R15): 128 CTAs (64 fwd + 64 rev) run the
// warp-skewed block pipeline over diags 0..1023, dump diag-1022/1023 values;
// combine_kernel does the exact cut softmin; reduce averages.
// R17: the per-superstep __syncthreads is replaced by intra-CTA DATAFLOW:
// each warp (band) runs its blocks back-to-back, synchronizing only with its
// neighbors via smem flags: prog[b] = last block band b published (STS row +
// threadfence_block + volatile store), consp[b] = last block band b consumed.
// Band b's block t waits for prog[b-1] >= t and consp[b+1] >= t-2 (slot reuse).
// Warp-converged spin via __all_sync; volatile reads on the consumer path.

#define NBATCH 64
#define NPTS   1024
#define TPB    256            // combine kernel block
#define DTPB   512
#define NW     16
#define KB     16
#define NBLK   64             // diagonals 0..1023 only
#define BIGV   1.0e30f
#define SENT   1.0e17f
#define LN2F   0.69314718055994531f
#define PAD    64
#define SCPN   1100           // scp indices used: [1, 1088]

__device__ float g_partial[NBATCH];
__device__ float g_cut[NBATCH][4][NPTS];   // 0=f1022, 1=f1023, 2=r1022, 3=r1023

__device__ __forceinline__ float ex2f(float x) {
    float r; asm("ex2.approx.ftz.f32 %0, %1;" : "=f"(r) : "f"(x)); return r;
}
__device__ __forceinline__ float lg2f(float x) {
    float r; asm("lg2.approx.ftz.f32 %0, %1;" : "=f"(r) : "f"(x)); return r;
}

// softmin in log2 domain: one exp arg is always 0 -> 2 ex2 + 1 lg2.
__device__ __forceinline__ float cellv(float a, float bq, float c, float Dl) {
    float t1  = fminf(a, bq);
    float t2  = fmaxf(a, bq);
    float mn  = fminf(t1, c);
    float mx  = fmaxf(t2, c);
    float mid = fminf(t2, fmaxf(t1, c));
    float s   = 1.0f + (ex2f(mn - mid) + ex2f(mn - mx));
    return Dl + (mn - lg2f(s));
}

typedef float BufT[2][NW][KB + 1];

template<bool LAST>
__device__ __forceinline__ void run_block16(
    BufT& bufk, int slot, int wid, int lane,
    const float4* pc, float4& cb,
    float& cur_a, float& cur_b, float& cur_a_old, float& nb2,
    float m2ax, float m2ay, float s2a,
    float m2bx, float m2by, float s2b,
    float& o22a, float& o22b)
{
    // Consumer strip reads are volatile: ordered after the spin by control
    // dependency; not cached stale by the compiler.
    const volatile float* src = &bufk[slot][(wid > 0) ? (wid - 1) : 0][0];
    #pragma unroll
    for (int k = 0; k < KB; ++k) {
        float nb1 = __shfl_up_sync(0xFFFFFFFFu, cur_b, 1);
        if (lane == 0) nb1 = (wid == 0) ? BIGV : src[k];

        float4 ca = pc[k];
        float Dla = fmaf(m2ay, ca.y, fmaf(m2ax, ca.x, s2a + ca.z));
        float Dlb = fmaf(m2by, cb.y, fmaf(m2bx, cb.x, s2b + cb.z));

        float new_a = cellv(nb2,       nb1,   cur_a, Dla);
        float new_b = cellv(cur_a_old, cur_a, cur_b, Dlb);

        if (lane == 31) bufk[slot][wid][k + 1] = new_b;

        nb2 = nb1; cur_a_old = cur_a; cur_a = new_a; cur_b = new_b;
        cb = ca;
        if (LAST && k == KB - 2) { o22a = cur_a; o22b = cur_b; }  // diag 1022
    }
}

__global__ __launch_bounds__(DTPB, 1)
void dtw_kernel(const float* __restrict__ snake, const float* __restrict__ contour)
{
    __shared__ float4 scp[SCPN];      // (cx, cy, cx^2+cy^2, 0), sentinel outside
    __shared__ BufT   bufk;
    __shared__ int    prog[NW];       // last block published by band b
    __shared__ int    consp[NW];      // last block consumed by band b

    const int tid  = threadIdx.x;
    const int lane = tid & 31;
    const int wid  = tid >> 5;
    const int rev  = blockIdx.x & 1;  // 0 = forward, 1 = reversed sequences
    const int b    = blockIdx.x >> 1;
    const float SCALE = 1.2011224087864498f;   // sqrt(log2 e)

    // scp[idx] <-> jp = idx - PAD; valid contour at jp in [1,1024].
    for (int k = tid; k < SCPN; k += DTPB) {
        int j = k - PAD;
        float cx = SENT, cy = SENT;
        if (j >= 1 && j <= NPTS) {
            int src = rev ? (NPTS - j) : (j - 1);
            float2 c = ((const float2*)contour)[b * NPTS + src];
            cx = c.x * SCALE; cy = c.y * SCALE;
        }
        scp[k] = make_float4(cx, cy, fmaf(cx, cx, cy * cy), 0.f);
    }
    for (int k = tid; k < 2 * NW * (KB + 1); k += DTPB)
        ((float*)bufk)[k] = BIGV;
    if (tid < NW) { prog[tid] = 4 * tid - 1; consp[tid] = 4 * tid - 1; }

    // Rows 2*tid, 2*tid+1 (in this CTA's orientation).
    const int row_a = 2 * tid;
    float sax, say, sbx, sby;
    if (!rev) {
        float4 s4 = ((const float4*)snake)[b * DTPB + tid];
        sax = s4.x * SCALE; say = s4.y * SCALE;
        sbx = s4.z * SCALE; sby = s4.w * SCALE;
    } else {
        float4 s4 = ((const float4*)snake)[b * DTPB + (DTPB - 1 - tid)];
        sax = s4.z * SCALE; say = s4.w * SCALE;   // orig row 1023-2tid
        sbx = s4.x * SCALE; sby = s4.y * SCALE;   // orig row 1022-2tid
    }
    const float m2ax = -2.f * sax, m2ay = -2.f * say;
    const float s2a  = fmaf(sax, sax, say * say);
    const float m2bx = -2.f * sbx, m2by = -2.f * sby;
    const float s2b  = fmaf(sbx, sbx, sby * sby);

    __syncthreads();                  // setup fence (only CTA-wide barrier)

    float cur_a = BIGV, cur_b = BIGV, cur_a_old = BIGV, nb2 = BIGV;
    if (tid == 0) nb2 = 0.0f;         // R(-1,-1)=0 => cell(0,0)=D(0,0)

    const int tLo = 4 * wid;          // blocks [4*wid, 63]
    const float4* pc = &scp[tLo * KB - row_a + 1 + PAD];
    float4 cb = pc[-1];
    float o22a = BIGV, o22b = BIGV;

    for (int t = tLo; t < NBLK; ++t) {
        // Dataflow waits: producer strip ready + our strip slot drained.
        for (;;) {
            bool ok = true;
            if (lane == 0 && wid > 0)
                ok = (*(volatile int*)&prog[wid - 1] >= t);
            if (lane == 31 && wid < NW - 1)
                ok = ok && (*(volatile int*)&consp[wid + 1] >= t - 2);
            if (__all_sync(0xFFFFFFFFu, ok)) break;
        }

        const int slot = t & 1;
        if (lane == 31) bufk[slot][wid][0] = cur_b;   // carry: diag t*KB-1
        if (t < NBLK - 1) {
            run_block16<false>(bufk, slot, wid, lane, pc, cb,
                               cur_a, cur_b, cur_a_old, nb2,
                               m2ax, m2ay, s2a, m2bx, m2by, s2b, o22a, o22b);
        } else {
            run_block16<true>(bufk, slot, wid, lane, pc, cb,
                              cur_a, cur_b, cur_a_old, nb2,
                              m2ax, m2ay, s2a, m2bx, m2by, s2b, o22a, o22b);
            // After block 63: cur_* = diag-1023 values, o22* = diag-1022.
            g_cut[b][2 * rev + 0][row_a]     = o22a;
            g_cut[b][2 * rev + 0][row_a + 1] = o22b;
            g_cut[b][2 * rev + 1][row_a]     = cur_a;
            g_cut[b][2 * rev + 1][row_a + 1] = cur_b;
        }
        pc += KB;

        // Publish: strip row visible before prog store; consumption after reads.
        if (lane == 31) {
            __threadfence_block();
            *(volatile int*)&prog[wid] = t;
        }
        if (lane == 0)
            *(volatile int*)&consp[wid] = t;
    }
}

__global__ __launch_bounds__(TPB)
void combine_kernel(const float* __restrict__ snake, const float* __restrict__ contour)
{
    __shared__ float red[64];
    const int b   = blockIdx.x;
    const int tid = threadIdx.x;
    const int lane = tid & 31, wid = tid >> 5;
    const float LOG2E = 1.4426950408889634f;

    float t[8];
    #pragma unroll
    for (int q = 0; q < 8; ++q) t[q] = BIGV;

    #pragma unroll
    for (int q = 0; q < 4; ++q) {
        int i = tid + q * TPB;                       // 0..1023
        float2 s = ((const float2*)snake)[b * NPTS + i];
        float2 c = ((const float2*)contour)[b * NPTS + (NPTS - 1 - i)];
        float dx = s.x - c.x, dy = s.y - c.y;
        float Dl = LOG2E * fmaf(dy, dy, dx * dx);
        t[q] = g_cut[b][1][i] + g_cut[b][3][NPTS - 1 - i] - Dl;
    }
    #pragma unroll
    for (int q = 0; q < 4; ++q) {
        int i = tid + q * TPB;
        if (i < NPTS - 1)                            // 0..1022
            t[4 + q] = g_cut[b][0][i] + g_cut[b][2][NPTS - 2 - i];
    }

    float m = t[0];
    #pragma unroll
    for (int q = 1; q < 8; ++q) m = fminf(m, t[q]);
    #pragma unroll
    for (int off = 16; off > 0; off >>= 1)
        m = fminf(m, __shfl_xor_sync(0xFFFFFFFFu, m, off));
    if (lane == 0) red[wid] = m;
    __syncthreads();
    if (tid == 0) {
        float mm = red[0];
        for (int w = 1; w < TPB / 32; ++w) mm = fminf(mm, red[w]);
        red[0] = mm;
    }
    __syncthreads();
    m = red[0];

    float S = 0.f;
    #pragma unroll
    for (int q = 0; q < 8; ++q) S += ex2f(m - t[q]);
    #pragma unroll
    for (int off = 16; off > 0; off >>= 1)
        S += __shfl_xor_sync(0xFFFFFFFFu, S, off);
    if (lane == 0) red[32 + wid] = S;
    __syncthreads();
    if (tid == 0) {
        float ss = 0.f;
        for (int w = 0; w < TPB / 32; ++w) ss += red[32 + w];
        g_partial[b] = (m - lg2f(ss)) * LN2F;        // softmin -> ln units
    }
}

__global__ void reduce_kernel(float* __restrict__ out)
{
    float v = g_partial[threadIdx.x] + g_partial[threadIdx.x + 32];
    #pragma unroll
    for (int off = 16; off > 0; off >>= 1)
        v += __shfl_down_sync(0xFFFFFFFFu, v, off);
    if (threadIdx.x == 0)
        out[0] = v * (1.0f / NBATCH);
}

extern "C" void kernel_launch(void* const* d_in, const int* in_sizes, int n_in,
                              void* d_out, int out_size)
{
    const float* snake   = (const float*)d_in[0];
    const float* contour = (const float*)d_in[1];
    float* out = (float*)d_out;

    dtw_kernel<<<NBATCH * 2, DTPB>>>(snake, contour);
    combine_kernel<<<NBATCH, TPB>>>(snake, contour);
    reduce_kernel<<<1, 32>>>(out);
}